// round 16
// baseline (speedup 1.0000x reference)
#include <cuda_runtime.h>
#include <cuda_bf16.h>
#include <cstdint>

// Problem constants (fixed by the dataset)
#define BDIM 76
#define NDIM 151
#define KNEI 10
#define HDIM 512
#define FB 5
#define FA 89
#define FAP 128                   // padded raw-input K
#define MN (BDIM * NDIM)          // 11476 nodes
#define MN2 (MN / 2)              // 5738 (two nodes per 256-thr block)
#define LDU2 (HDIM + FB)          // 517
#define LDU1 (2 * HDIM)           // 1024
#define KS 8                      // chain split-K factor

// ---------------- static device scratch (no allocation allowed) -------------
__device__ __align__(128) float g_sb[MN * 8], g_Ssb[MN * 8], g_SSsb[MN * 8];
__device__ __align__(128) float g_wc8[HDIM * 8], g_P1[HDIM * 8], g_P2[HDIM * 8];
__device__ __align__(128) float g_R0[HDIM * 8], g_R1[HDIM * 8], g_R2[HDIM * 8];
__device__ __align__(128) float g_Wf[HDIM * HDIM];
__device__ __align__(128) float g_SX[MN * FAP], g_SSX[MN * FAP];
__device__ __align__(128) float g_part[KS * HDIM * HDIM];  // split-K partials (8MB)

__device__ __align__(128) __nv_bfloat16 g_Xhi[MN * FAP],   g_Xlo[MN * FAP];
__device__ __align__(128) __nv_bfloat16 g_SXhi[MN * FAP],  g_SXlo[MN * FAP];
__device__ __align__(128) __nv_bfloat16 g_SSXhi[MN * FAP], g_SSXlo[MN * FAP];
__device__ __align__(128) __nv_bfloat16 g_S3Xhi[MN * FAP], g_S3Xlo[MN * FAP];
__device__ __align__(128) __nv_bfloat16 g_Wahi[HDIM * HDIM], g_Walo[HDIM * HDIM];
__device__ __align__(128) __nv_bfloat16 g_Wbhi[HDIM * HDIM], g_Wblo[HDIM * HDIM];
__device__ __align__(128) __nv_bfloat16 g_Wthi[HDIM * HDIM], g_Wtlo[HDIM * HDIM];
__device__ __align__(128) __nv_bfloat16 g_Wfhi[HDIM * HDIM], g_Wflo[HDIM * HDIM];
__device__ __align__(128) __nv_bfloat16 g_Wethi[FAP * HDIM], g_Wetlo[FAP * HDIM];
// chain intermediates, in-major [128,512]
__device__ __align__(128) __nv_bfloat16 g_Uhi[FAP * HDIM],   g_Ulo[FAP * HDIM];
__device__ __align__(128) __nv_bfloat16 g_Vhi[FAP * HDIM],   g_Vlo[FAP * HDIM];
__device__ __align__(128) __nv_bfloat16 g_U20hi[FAP * HDIM], g_U20lo[FAP * HDIM];
__device__ __align__(128) __nv_bfloat16 g_U21hi[FAP * HDIM], g_U21lo[FAP * HDIM];
__device__ __align__(128) __nv_bfloat16 g_U22hi[FAP * HDIM], g_U22lo[FAP * HDIM];
// transposed T weights, B-format [512,128]
__device__ __align__(128) __nv_bfloat16 g_Tthi[4][HDIM * FAP], g_Ttlo[4][HDIM * FAP];

// ======================= PTX helpers (sm_80-safe only) ======================
__device__ __forceinline__ uint32_t smem_u32(const void* p) {
    uint32_t a;
    asm("{ .reg .u64 t; cvta.to.shared.u64 t, %1; cvt.u32.u64 %0, t; }"
        : "=r"(a) : "l"(p));
    return a;
}
__device__ __forceinline__ void cp_async16(uint32_t dst, const void* src, int sz) {
    asm volatile("cp.async.cg.shared.global [%0], [%1], 16, %2;"
                 :: "r"(dst), "l"(src), "r"(sz) : "memory");
}
__device__ __forceinline__ void ldsm_x4(uint32_t addr, uint32_t* r) {
    asm volatile("ldmatrix.sync.aligned.m8n8.x4.shared.b16 {%0,%1,%2,%3}, [%4];"
                 : "=r"(r[0]), "=r"(r[1]), "=r"(r[2]), "=r"(r[3]) : "r"(addr));
}
__device__ __forceinline__ void mma_bf16(float* c, const uint32_t* a,
                                         uint32_t b0, uint32_t b1) {
    asm volatile(
        "mma.sync.aligned.m16n8k16.row.col.f32.bf16.bf16.f32 "
        "{%0,%1,%2,%3}, {%4,%5,%6,%7}, {%8,%9}, {%0,%1,%2,%3};"
        : "+f"(c[0]), "+f"(c[1]), "+f"(c[2]), "+f"(c[3])
        : "r"(a[0]), "r"(a[1]), "r"(a[2]), "r"(a[3]), "r"(b0), "r"(b1));
}
__device__ __forceinline__ __nv_bfloat162 split_hi2(float x, float y,
                                                    __nv_bfloat162& lo2) {
    const __nv_bfloat16 hx = __float2bfloat16_rn(x);
    const __nv_bfloat16 hy = __float2bfloat16_rn(y);
    lo2 = __nv_bfloat162(__float2bfloat16_rn(x - __bfloat162float(hx)),
                         __float2bfloat16_rn(y - __bfloat162float(hy)));
    return __nv_bfloat162(hx, hy);
}
__device__ __forceinline__ float dot8(const float* s, const float* w) {
    return s[0]*w[0] + s[1]*w[1] + s[2]*w[2] + s[3]*w[3]
         + s[4]*w[4] + s[5]*w[5] + s[6]*w[6] + s[7]*w[7];
}

// ============ fused bf16x3 mma GEMM, 128x64 tiles ===========================
// Per z and group g: C += Ahi@Bhi^T + Alo@Bhi^T + Ahi@Blo^T
// KCH: K elements per stage chunk (64 or 32). Stage = 384 rows x KCH*2 bytes.
// Swizzle: 128B rows -> ch^=(row&7); 64B rows -> ch^=((row>>1)&3).
// DUAL: dual accumulators (chain) vs single (mega, lower regs for OCC=3).
#define STG_B(KCH) (384 * (KCH) * 2)

struct Grp { const __nv_bfloat16 *ahi, *alo, *bhi, *blo; };
struct BatchArgs {
    Grp g[4][4];                       // [z][group]
    int ng[4];
    float* outC[4];
};

template <int KCH, int KCPP, int LDA, int LDC, bool RANK24, int NSTAGE,
          int KSPLIT, bool DUAL, int OCC>
__global__ __launch_bounds__(256, OCC)
void mma_gemm64(const BatchArgs ba, int partElems,
                const float* __restrict__ sb0, const float* __restrict__ sb1,
                const float* __restrict__ sb2,
                const float* __restrict__ R0, const float* __restrict__ R1,
                const float* __restrict__ R2, int M) {
    extern __shared__ __align__(128) char smem[];
    constexpr int RB = KCH * 2;          // row bytes
    constexpr int CPR = KCH / 8;         // 16B chunks per row (8 or 4)
    constexpr int STG = 384 * RB;
    const uint32_t sbase = smem_u32(smem);
    const int z = blockIdx.z;
    const Grp* G = ba.g[z];
    const int tid = threadIdx.x, wid = tid >> 5, lane = tid & 31;
    const int kslice = (KSPLIT > 1) ? ((int)blockIdx.y % KSPLIT) : 0;
    const int bm = ((KSPLIT > 1) ? ((int)blockIdx.y / KSPLIT) : blockIdx.y) * 128;
    const int bn = blockIdx.x * 64;
    const int wm = (wid & 3) * 32;
    const int wn = (wid >> 2) * 32;

    float accA[2][4][4] = {};
    float accB[DUAL ? 2 : 1][4][4] = {};

    auto swz = [](int row, int ch) {
        return (KCH == 64) ? (ch ^ (row & 7)) : (ch ^ ((row >> 1) & 3));
    };

    const int lrow0 = tid / CPR;
    const int lch = tid % CPR;
    auto load_stage = [&](int g, int s) {
        const int grp = g / KCPP, kc = g % KCPP;
        const uint32_t sbs = sbase + s * STG;
        const __nv_bfloat16* TA[2] = { G[grp].ahi, G[grp].alo };
        #pragma unroll
        for (int t = 0; t < 2; ++t) {
            const uint32_t tb = sbs + t * (128 * RB);
            #pragma unroll
            for (int it = 0; it < CPR / 2; ++it) {
                const int row = lrow0 + it * (256 / CPR);
                const uint32_t soff = row * RB + (swz(row, lch) << 4);
                const long gr = bm + row;
                cp_async16(tb + soff, TA[t] + gr * LDA + kc * KCH + lch * 8,
                           (gr < M) ? 16 : 0);
            }
        }
        const __nv_bfloat16* TB[2] = { G[grp].bhi, G[grp].blo };
        #pragma unroll
        for (int t = 0; t < 2; ++t) {
            const uint32_t tb = sbs + 256 * RB + t * (64 * RB);
            #pragma unroll
            for (int it = 0; it < (CPR + 3) / 4; ++it) {
                const int row = (CPR == 8) ? (lrow0 + it * 32) : lrow0;
                const uint32_t soff = row * RB + (swz(row, lch) << 4);
                const long gr = bn + row;
                cp_async16(tb + soff, TB[t] + gr * LDA + kc * KCH + lch * 8, 16);
            }
        }
        asm volatile("cp.async.commit_group;" ::: "memory");
    };

    auto compute_stage = [&](int s) {
        const uint32_t sah = sbase + s * STG;
        const uint32_t sal = sah + 128 * RB;
        const uint32_t sbh = sah + 256 * RB;
        const uint32_t sbl = sah + 320 * RB;
        #pragma unroll
        for (int ks = 0; ks < KCH / 16; ++ks) {
            const int ach = ks * 2 + (lane >> 4);
            uint32_t rah[2][4], ral[2][4];
            #pragma unroll
            for (int mb = 0; mb < 2; ++mb) {
                const int row = wm + mb * 16 + (lane & 15);
                const uint32_t off = row * RB + (swz(row, ach) << 4);
                ldsm_x4(sah + off, rah[mb]);
                ldsm_x4(sal + off, ral[mb]);
            }
            uint32_t rbh[2][4], rbl[2][4];
            #pragma unroll
            for (int nb = 0; nb < 2; ++nb) {
                const int row = wn + nb * 16 + (lane & 15);
                const uint32_t off = row * RB + (swz(row, ach) << 4);
                ldsm_x4(sbh + off, rbh[nb]);
                ldsm_x4(sbl + off, rbl[nb]);
            }
            #pragma unroll
            for (int mb = 0; mb < 2; ++mb)
                #pragma unroll
                for (int nb = 0; nb < 2; ++nb) {
                    mma_bf16(accA[mb][nb * 2],     rah[mb], rbh[nb][0], rbh[nb][2]);
                    mma_bf16(accA[mb][nb * 2 + 1], rah[mb], rbh[nb][1], rbh[nb][3]);
                }
            #pragma unroll
            for (int mb = 0; mb < 2; ++mb)
                #pragma unroll
                for (int nb = 0; nb < 2; ++nb) {
                    float* d0 = DUAL ? accB[mb][nb * 2] : accA[mb][nb * 2];
                    float* d1 = DUAL ? accB[mb][nb * 2 + 1] : accA[mb][nb * 2 + 1];
                    mma_bf16(d0, ral[mb], rbh[nb][0], rbh[nb][2]);
                    mma_bf16(d1, ral[mb], rbh[nb][1], rbh[nb][3]);
                }
            #pragma unroll
            for (int mb = 0; mb < 2; ++mb)
                #pragma unroll
                for (int nb = 0; nb < 2; ++nb) {
                    float* d0 = DUAL ? accB[mb][nb * 2] : accA[mb][nb * 2];
                    float* d1 = DUAL ? accB[mb][nb * 2 + 1] : accA[mb][nb * 2 + 1];
                    mma_bf16(d0, rah[mb], rbl[nb][0], rbl[nb][2]);
                    mma_bf16(d1, rah[mb], rbl[nb][1], rbl[nb][3]);
                }
        }
    };

    const int NGt = ba.ng[z] * KCPP;
    const int per = (KSPLIT > 1) ? NGt / KSPLIT : NGt;
    const int g0 = kslice * per;
    load_stage(g0, g0 % NSTAGE);
    if (NSTAGE >= 3 && per > 1) load_stage(g0 + 1, (g0 + 1) % NSTAGE);
    for (int gi = 0; gi < per; ++gi) {
        const int g = g0 + gi;
        if (NSTAGE == 2) {
            if (gi + 1 < per) {
                load_stage(g + 1, (g + 1) % NSTAGE);
                asm volatile("cp.async.wait_group 1;" ::: "memory");
            } else {
                asm volatile("cp.async.wait_group 0;" ::: "memory");
            }
        } else {
            if (gi + 2 < per) {
                load_stage(g + 2, (g + 2) % NSTAGE);
                asm volatile("cp.async.wait_group 2;" ::: "memory");
            } else if (gi + 1 < per) {
                asm volatile("cp.async.wait_group 1;" ::: "memory");
            } else {
                asm volatile("cp.async.wait_group 0;" ::: "memory");
            }
        }
        __syncthreads();
        compute_stage(g % NSTAGE);
        __syncthreads();
    }

    if (RANK24) {
        #pragma unroll
        for (int t = 0; t < 3; ++t) {
            const float* sbp = (t == 0) ? sb0 : (t == 1) ? sb1 : sb2;
            const float* Rp  = (t == 0) ? R0  : (t == 1) ? R1  : R2;
            float sv[4][8];
            #pragma unroll
            for (int r = 0; r < 4; ++r) {
                const int gm = bm + wm + (r >> 1) * 16 + (lane >> 2) + (r & 1) * 8;
                if (gm < M) {
                    *(float4*)&sv[r][0] = *(const float4*)&sbp[gm * 8];
                    *(float4*)&sv[r][4] = *(const float4*)&sbp[gm * 8 + 4];
                } else {
                    #pragma unroll
                    for (int j = 0; j < 8; ++j) sv[r][j] = 0.f;
                }
            }
            #pragma unroll
            for (int nb = 0; nb < 4; ++nb) {
                const int gn = bn + wn + nb * 8 + (lane & 3) * 2;
                float w0[8], w1[8];
                *(float4*)&w0[0] = *(const float4*)&Rp[gn * 8];
                *(float4*)&w0[4] = *(const float4*)&Rp[gn * 8 + 4];
                *(float4*)&w1[0] = *(const float4*)&Rp[(gn + 1) * 8];
                *(float4*)&w1[4] = *(const float4*)&Rp[(gn + 1) * 8 + 4];
                #pragma unroll
                for (int mb = 0; mb < 2; ++mb)
                    #pragma unroll
                    for (int h = 0; h < 2; ++h) {
                        const int r = mb * 2 + h;
                        accA[mb][nb][h * 2]     += dot8(sv[r], w0);
                        accA[mb][nb][h * 2 + 1] += dot8(sv[r], w1);
                    }
            }
        }
    }

    float* C = ba.outC[z] + ((KSPLIT > 1) ? (long)kslice * partElems : 0);
    #pragma unroll
    for (int nb = 0; nb < 4; ++nb) {
        const int gn = bn + wn + nb * 8 + (lane & 3) * 2;
        #pragma unroll
        for (int mb = 0; mb < 2; ++mb)
            #pragma unroll
            for (int h = 0; h < 2; ++h) {
                const int gm = bm + wm + mb * 16 + (lane >> 2) + h * 8;
                if (gm < M) {
                    float vx = accA[mb][nb][h * 2];
                    float vy = accA[mb][nb][h * 2 + 1];
                    if (DUAL) {
                        vx += accB[mb][nb][h * 2];
                        vy += accB[mb][nb][h * 2 + 1];
                    }
                    *(float2*)&C[(long)gm * LDC + gn] = make_float2(vx, vy);
                }
            }
    }
}

// ================= device sub-kernels (merged-launch parts) =================
__device__ void do_prep0(int b, int tid,
                         const float* __restrict__ W_U1,
                         const float* __restrict__ W_U2,
                         const float* __restrict__ W_atom,
                         const float* __restrict__ b_U2,
                         const float* __restrict__ b_U1, float* sh) {
    if (b < 2048) {
        const int koff = (b < 1024) ? 0 : HDIM;
        __nv_bfloat16* hi = (b < 1024) ? g_Wahi : g_Wbhi;
        __nv_bfloat16* lo = (b < 1024) ? g_Walo : g_Wblo;
        const int idx = (b & 1023) * 256 + tid;
        const int n = idx >> 9, k = idx & 511;
        const float v = __ldg(&W_U1[(long)n * LDU1 + koff + k]);
        const __nv_bfloat16 h = __float2bfloat16_rn(v);
        hi[idx] = h;
        lo[idx] = __float2bfloat16_rn(v - __bfloat162float(h));
    } else if (b < 2304) {
        const int bb = b - 2048;
        const int bx = (bb & 15) * 32, by = (bb >> 4) * 32;
        const int x = tid & 31, y = tid >> 5;
        #pragma unroll
        for (int i = 0; i < 32; i += 8)
            sh[(y + i) * 33 + x] = __ldg(&W_U2[(long)(by + y + i) * LDU2 + bx + x]);
        __syncthreads();
        #pragma unroll
        for (int i = 0; i < 32; i += 8) {
            const float v = sh[x * 33 + y + i];
            const __nv_bfloat16 h = __float2bfloat16_rn(v);
            const long o = (long)(bx + y + i) * HDIM + by + x;
            g_Wthi[o] = h;
            g_Wtlo[o] = __float2bfloat16_rn(v - __bfloat162float(h));
        }
    } else if (b < 2352) {
        const int bb = b - 2304;
        const int bm = (bb % 16) * 32, bf = (bb / 16) * 32;
        const int x = tid & 31, y = tid >> 5;
        #pragma unroll
        for (int i = 0; i < 32; i += 8) {
            const int m = bm + y + i, f = bf + x;
            sh[(y + i) * 33 + x] = (f < FA) ? __ldg(&W_atom[(long)m * FA + f]) : 0.f;
        }
        __syncthreads();
        #pragma unroll
        for (int i = 0; i < 32; i += 8) {
            const int f = bf + y + i, m = bm + x;
            if (f < FA) {
                const float v = sh[x * 33 + y + i];
                const __nv_bfloat16 h = __float2bfloat16_rn(v);
                const long o = (long)f * HDIM + m;
                g_Wethi[o] = h;
                g_Wetlo[o] = __float2bfloat16_rn(v - __bfloat162float(h));
            }
        }
    } else {
        const int h = b - 2352;
        const int w = tid >> 5, lane = tid & 31;
        float acc[6] = {};
        #pragma unroll
        for (int j = 0; j < 2; ++j) {
            const int m = tid + 256 * j;
            const float u = __ldg(&W_U1[(long)h * LDU1 + HDIM + m]);
            #pragma unroll
            for (int f = 0; f < FB; ++f)
                acc[f] += u * __ldg(&W_U2[(long)m * LDU2 + HDIM + f]);
            acc[5] += u * __ldg(&b_U2[m]);
        }
        #pragma unroll
        for (int f = 0; f < 6; ++f)
            #pragma unroll
            for (int o = 16; o; o >>= 1)
                acc[f] += __shfl_xor_sync(0xFFFFFFFF, acc[f], o);
        if (lane == 0)
            #pragma unroll
            for (int f = 0; f < 6; ++f) sh[w * 8 + f] = acc[f];
        __syncthreads();
        if (tid == 0) {
            float r[6];
            #pragma unroll
            for (int f = 0; f < 6; ++f) {
                r[f] = 0.f;
                #pragma unroll
                for (int ww = 0; ww < 8; ++ww) r[f] += sh[ww * 8 + f];
            }
            *(float4*)&g_wc8[h * 8] = make_float4(r[0], r[1], r[2], r[3]);
            *(float4*)&g_wc8[h * 8 + 4] = make_float4(r[4], r[5],
                                                      __ldg(&b_U1[h]), 0.f);
        }
    }
}

__device__ void do_pgather(int node, int c,
                           const float* __restrict__ P,
                           const float* __restrict__ input_bond,
                           const int* __restrict__ aidx,
                           const int* __restrict__ bidx,
                           const int* __restrict__ num_nbs) {
    const int base = (node / NDIM) * NDIM;
    const int nn = num_nbs[node];
    const float v = (c < FA) ? __ldg(&P[(long)node * FA + c]) : 0.f;
    const __nv_bfloat16 vh = __float2bfloat16_rn(v);
    g_Xhi[(long)node * FAP + c] = vh;
    g_Xlo[(long)node * FAP + c] = __float2bfloat16_rn(v - __bfloat162float(vh));

    float s = 0.f;
    if (c < FA) {
        #pragma unroll
        for (int k = 0; k < KNEI; ++k) {
            if (k >= nn) break;
            const int idx = __ldg(&aidx[((long)node * KNEI + k) * 2]);
            s += __ldg(&P[(long)(base + idx) * FA + c]);
        }
    }
    g_SX[(long)node * FAP + c] = s;
    const __nv_bfloat16 sh = __float2bfloat16_rn(s);
    g_SXhi[(long)node * FAP + c] = sh;
    g_SXlo[(long)node * FAP + c] = __float2bfloat16_rn(s - __bfloat162float(sh));

    if (c < 8) {
        float sv;
        if (c < FB) {
            sv = 0.f;
            for (int k = 0; k < nn; ++k) {
                const int idx = __ldg(&bidx[((long)node * KNEI + k) * 2]);
                sv += __ldg(&input_bond[(long)(base + idx) * FB + c]);
            }
        } else sv = (c == 5) ? (float)nn : (c == 6) ? 1.f : 0.f;
        g_sb[node * 8 + c] = sv;
    }
}

__device__ void do_gatherK(int node, int c, bool wf32,
                           const float* __restrict__ in, float* __restrict__ outf,
                           __nv_bfloat16* __restrict__ ohi,
                           __nv_bfloat16* __restrict__ olo,
                           const float* __restrict__ sbin, float* __restrict__ sbout,
                           const int* __restrict__ aidx,
                           const int* __restrict__ num_nbs) {
    const int base = (node / NDIM) * NDIM;
    const int nn = num_nbs[node];
    float s = 0.f;
    float sb = 0.f;
    #pragma unroll
    for (int k = 0; k < KNEI; ++k) {
        if (k >= nn) break;
        const int idx = __ldg(&aidx[((long)node * KNEI + k) * 2]);
        s += __ldg(&in[(long)(base + idx) * FAP + c]);
        if (c < 8) sb += __ldg(&sbin[(base + idx) * 8 + c]);
    }
    if (wf32) outf[(long)node * FAP + c] = s;
    const __nv_bfloat16 sh = __float2bfloat16_rn(s);
    ohi[(long)node * FAP + c] = sh;
    olo[(long)node * FAP + c] = __float2bfloat16_rn(s - __bfloat162float(sh));
    if (c < 8) sbout[node * 8 + c] = sb;
}

__device__ void do_reduce_wf(int b, int tid) {
    const int i = (b * 256 + tid) * 2;
    float2 s = make_float2(0.f, 0.f);
    #pragma unroll
    for (int sl = 0; sl < KS; ++sl) {
        const float2 v = *(const float2*)&g_part[sl * (HDIM * HDIM) + i];
        s.x += v.x; s.y += v.y;
    }
    *(float2*)&g_Wf[i] = s;
    __nv_bfloat162 lo2;
    const __nv_bfloat162 hi2 = split_hi2(s.x, s.y, lo2);
    *(__nv_bfloat162*)&g_Wfhi[i] = hi2;
    *(__nv_bfloat162*)&g_Wflo[i] = lo2;
}

__device__ void do_reduce_split(int z, int bi, int tid,
                                __nv_bfloat16* hi, __nv_bfloat16* lo) {
    const int i = (bi * 256 + tid) * 2;
    const float* base = g_part + (long)(z * KS) * (FAP * HDIM);
    float2 s = make_float2(0.f, 0.f);
    #pragma unroll
    for (int sl = 0; sl < KS; ++sl) {
        const float2 v = *(const float2*)&base[sl * (FAP * HDIM) + i];
        s.x += v.x; s.y += v.y;
    }
    __nv_bfloat162 lo2;
    const __nv_bfloat162 hi2 = split_hi2(s.x, s.y, lo2);
    *(__nv_bfloat162*)&hi[i] = hi2;
    *(__nv_bfloat162*)&lo[i] = lo2;
}

__device__ void do_rankA(int blk, int tid, const float* __restrict__ W_U1) {
    const int w = tid >> 5, lane = tid & 31;
    const int n = blk * 4 + (w & 3);
    const bool useWf = (w >> 2) != 0;
    float acc[8] = {};
    for (int m = lane; m < HDIM; m += 32) {
        const float u = useWf ? g_Wf[(long)n * HDIM + m]
                              : __ldg(&W_U1[(long)n * LDU1 + m]);
        #pragma unroll
        for (int j = 0; j < 8; ++j) acc[j] += u * g_wc8[m * 8 + j];
    }
    #pragma unroll
    for (int j = 0; j < 8; ++j)
        #pragma unroll
        for (int o = 16; o; o >>= 1)
            acc[j] += __shfl_xor_sync(0xFFFFFFFF, acc[j], o);
    if (lane == 0) {
        float* dst = useWf ? g_P2 : g_P1;
        #pragma unroll
        for (int j = 0; j < 8; ++j) dst[n * 8 + j] = acc[j];
    }
}

__device__ void do_rankB(int blk, int tid, const float* __restrict__ W_U1,
                         float* sh) {
    const int w = tid >> 5, lane = tid & 31;
    const int half = w >> 2;
    const int role = w & 3;
    const int n = blk * 2 + half;
    const bool useWa = (role == 0 || role == 2);
    const bool usePw = (role < 2);
    float acc[8] = {};
    for (int m = lane; m < HDIM; m += 32) {
        const float u = useWa ? __ldg(&W_U1[(long)n * LDU1 + m])
                              : g_Wf[(long)n * HDIM + m];
        #pragma unroll
        for (int j = 0; j < 8; ++j) {
            const float rv = usePw ? (g_P1[m * 8 + j] + g_wc8[m * 8 + j])
                                   : g_P2[m * 8 + j];
            acc[j] += u * rv;
        }
    }
    #pragma unroll
    for (int j = 0; j < 8; ++j)
        #pragma unroll
        for (int o = 16; o; o >>= 1)
            acc[j] += __shfl_xor_sync(0xFFFFFFFF, acc[j], o);
    if (lane == 0)
        #pragma unroll
        for (int j = 0; j < 8; ++j) sh[(half * 4 + role) * 8 + j] = acc[j];
    __syncthreads();
    if (lane == 0 && role == 0) {
        const float* bsh = &sh[half * 4 * 8];
        #pragma unroll
        for (int j = 0; j < 8; ++j) {
            g_R0[n * 8 + j] = bsh[0 * 8 + j] + g_wc8[n * 8 + j];
            g_R1[n * 8 + j] = bsh[2 * 8 + j] + bsh[1 * 8 + j];
            g_R2[n * 8 + j] = bsh[3 * 8 + j];
        }
    }
}

// ================= merged launch kernels ====================================
__global__ __launch_bounds__(256)
void k1_prep_pgather(const float* __restrict__ W_U1,
                     const float* __restrict__ W_U2,
                     const float* __restrict__ W_atom,
                     const float* __restrict__ b_U2,
                     const float* __restrict__ b_U1,
                     const float* __restrict__ input_atom,
                     const float* __restrict__ input_bond,
                     const int* __restrict__ aidx,
                     const int* __restrict__ bidx,
                     const int* __restrict__ num_nbs) {
    __shared__ float sh[32 * 33];
    const int b = blockIdx.x, tid = threadIdx.x;
    if (b < 2864) {
        do_prep0(b, tid, W_U1, W_U2, W_atom, b_U2, b_U1, sh);
    } else {
        const int node = (b - 2864) * 2 + (tid >> 7);
        do_pgather(node, tid & 127, input_atom, input_bond, aidx, bidx, num_nbs);
    }
}

__global__ __launch_bounds__(256)
void k2_redwf_gather1(const int* __restrict__ aidx,
                      const int* __restrict__ num_nbs) {
    const int b = blockIdx.x, tid = threadIdx.x;
    if (b < 512) {
        do_reduce_wf(b, tid);
    } else {
        const int node = (b - 512) * 2 + (tid >> 7);
        do_gatherK(node, tid & 127, true, g_SX, g_SSX, g_SSXhi, g_SSXlo,
                   g_sb, g_Ssb, aidx, num_nbs);
    }
}

__global__ __launch_bounds__(256)
void k3_reduv_rankA_gather2(const float* __restrict__ W_U1,
                            const int* __restrict__ aidx,
                            const int* __restrict__ num_nbs) {
    const int b = blockIdx.x, tid = threadIdx.x;
    if (b < 256) {
        const int z = b >> 7, bi = b & 127;
        do_reduce_split(z, bi, tid, z ? g_Vhi : g_Uhi, z ? g_Vlo : g_Ulo);
    } else if (b < 384) {
        do_rankA(b - 256, tid, W_U1);
    } else {
        const int node = (b - 384) * 2 + (tid >> 7);
        do_gatherK(node, tid & 127, false, g_SSX, nullptr, g_S3Xhi, g_S3Xlo,
                   g_Ssb, g_SSsb, aidx, num_nbs);
    }
}

__global__ __launch_bounds__(256)
void k4_redu2_rankB(const float* __restrict__ W_U1) {
    __shared__ float sh[64];
    const int b = blockIdx.x, tid = threadIdx.x;
    if (b < 384) {
        const int z = b >> 7, bi = b & 127;
        __nv_bfloat16* hi = (z == 0) ? g_U20hi : (z == 1) ? g_U21hi : g_U22hi;
        __nv_bfloat16* lo = (z == 0) ? g_U20lo : (z == 1) ? g_U21lo : g_U22lo;
        do_reduce_split(z, bi, tid, hi, lo);
    } else {
        do_rankB(b - 384, tid, W_U1, sh);
    }
}

__global__ __launch_bounds__(256)
void reduce_T_kernel() {
    __shared__ float sh[32 * 33];
    const int z = blockIdx.z;
    const float* base = g_part + (long)(z * KS) * (FAP * HDIM);
    __nv_bfloat16* ohi = g_Tthi[z];
    __nv_bfloat16* olo = g_Ttlo[z];
    const int bn = blockIdx.x * 32, bk = blockIdx.y * 32;
    const int x = threadIdx.x & 31, y = threadIdx.x >> 5;
    #pragma unroll
    for (int i = 0; i < 32; i += 8) {
        float s = 0.f;
        #pragma unroll
        for (int sl = 0; sl < KS; ++sl)
            s += __ldg(&base[sl * (FAP * HDIM) + (bk + y + i) * HDIM + bn + x]);
        sh[(y + i) * 33 + x] = s;
    }
    __syncthreads();
    #pragma unroll
    for (int i = 0; i < 32; i += 8) {
        const float v = sh[x * 33 + y + i];
        const __nv_bfloat16 h = __float2bfloat16_rn(v);
        const long o = (long)(bn + y + i) * FAP + bk + x;
        ohi[o] = h;
        olo[o] = __float2bfloat16_rn(v - __bfloat162float(h));
    }
}

// ======================= host ===============================================
extern "C" void kernel_launch(void* const* d_in, const int* in_sizes, int n_in,
                              void* d_out, int out_size) {
    const float* input_atom = (const float*)d_in[0];
    const float* input_bond = (const float*)d_in[1];
    const int*   atom_nei   = (const int*)d_in[2];
    const int*   bond_nei   = (const int*)d_in[3];
    const int*   num_nbs    = (const int*)d_in[4];
    const float* W_atom     = (const float*)d_in[5];
    const float* W_U2       = (const float*)d_in[6];
    const float* b_U2       = (const float*)d_in[7];
    const float* W_U1       = (const float*)d_in[8];
    const float* b_U1       = (const float*)d_in[9];
    float* out = (float*)d_out;

    #define GA(p, s) cudaGetSymbolAddress((void**)&p, s)
    float *sb, *Ssb, *SSsb, *R0, *R1, *R2, *part;
    GA(sb, g_sb); GA(Ssb, g_Ssb); GA(SSsb, g_SSsb);
    GA(R0, g_R0); GA(R1, g_R1); GA(R2, g_R2); GA(part, g_part);
    __nv_bfloat16 *Xhi, *Xlo, *SXhi, *SXlo, *SSXhi, *SSXlo, *S3Xhi, *S3Xlo;
    GA(Xhi, g_Xhi); GA(Xlo, g_Xlo); GA(SXhi, g_SXhi); GA(SXlo, g_SXlo);
    GA(SSXhi, g_SSXhi); GA(SSXlo, g_SSXlo); GA(S3Xhi, g_S3Xhi); GA(S3Xlo, g_S3Xlo);
    __nv_bfloat16 *Wahi, *Walo, *Wbhi, *Wblo, *Wthi, *Wtlo, *Wfhi, *Wflo;
    __nv_bfloat16 *Wethi, *Wetlo;
    GA(Wahi, g_Wahi); GA(Walo, g_Walo); GA(Wbhi, g_Wbhi); GA(Wblo, g_Wblo);
    GA(Wthi, g_Wthi); GA(Wtlo, g_Wtlo); GA(Wfhi, g_Wfhi); GA(Wflo, g_Wflo);
    GA(Wethi, g_Wethi); GA(Wetlo, g_Wetlo);
    __nv_bfloat16 *Uhi, *Ulo, *Vhi, *Vlo;
    __nv_bfloat16 *U20hi, *U20lo, *U21hi, *U21lo, *U22hi, *U22lo;
    GA(Uhi, g_Uhi); GA(Ulo, g_Ulo); GA(Vhi, g_Vhi); GA(Vlo, g_Vlo);
    GA(U20hi, g_U20hi); GA(U20lo, g_U20lo); GA(U21hi, g_U21hi);
    GA(U21lo, g_U21lo); GA(U22hi, g_U22hi); GA(U22lo, g_U22lo);
    __nv_bfloat16 (*Tthi)[HDIM * FAP], (*Ttlo)[HDIM * FAP];
    GA(Tthi, g_Tthi); GA(Ttlo, g_Ttlo);
    #undef GA

    // chain: KCH=64, dual-acc, OCC=2.   mega: KCH=32, single-acc, OCC=3.
    cudaFuncSetAttribute(
        (const void*)mma_gemm64<64, 8, 512, 512, false, 2, KS, true, 2>,
        cudaFuncAttributeMaxDynamicSharedMemorySize, 2 * STG_B(64));
    cudaFuncSetAttribute(
        (const void*)mma_gemm64<32, 4, 128, 512, true, 2, 1, false, 3>,
        cudaFuncAttributeMaxDynamicSharedMemorySize, 2 * STG_B(32));

    const dim3 thr(256);
    const int PE_S = FAP * HDIM;            // 65536 (chain round partial)
    const int PE_W = HDIM * HDIM;           // 262144 (Wf partial)

    // K1: fused prep + pgather
    k1_prep_pgather<<<2864 + MN2, thr>>>(W_U1, W_U2, W_atom, b_U2, b_U1,
                                         input_atom, input_bond,
                                         atom_nei, bond_nei, num_nbs);

    // round 0 (split-K): Wf partials = W_U1b @ W_U2a
    {
        BatchArgs ba{};
        ba.g[0][0] = { Wbhi, Wblo, Wthi, Wtlo };
        ba.ng[0] = 1; ba.outC[0] = part;
        mma_gemm64<64, 8, 512, 512, false, 2, KS, true, 2>
            <<<dim3(8, 4 * KS, 1), thr, 2 * STG_B(64)>>>(
            ba, PE_W, nullptr, nullptr, nullptr, nullptr, nullptr, nullptr, HDIM);
    }

    // K2: reduce_wf + gatherK1 (SSX)
    k2_redwf_gather1<<<512 + MN2, thr>>>(atom_nei, num_nbs);

    // round 1 (split-K): {U, V} = Wet o {Wa, Wf}
    {
        BatchArgs ba{};
        ba.g[0][0] = { Wethi, Wetlo, Wahi, Walo };
        ba.g[1][0] = { Wethi, Wetlo, Wfhi, Wflo };
        ba.ng[0] = ba.ng[1] = 1;
        ba.outC[0] = part;
        ba.outC[1] = part + (long)KS * PE_S;
        mma_gemm64<64, 8, 512, 512, false, 2, KS, true, 2>
            <<<dim3(8, KS, 2), thr, 2 * STG_B(64)>>>(
            ba, PE_S, nullptr, nullptr, nullptr, nullptr, nullptr, nullptr, FAP);
    }

    // K3: reduce{U,V} + rankA + gatherK2 (S3X)
    k3_reduv_rankA_gather2<<<384 + MN2, thr>>>(W_U1, atom_nei, num_nbs);

    // round 2 (split-K): {U20, U21, U22}
    {
        BatchArgs ba{};
        ba.g[0][0] = { Uhi, Ulo, Wahi, Walo };                        ba.ng[0] = 1;
        ba.g[1][0] = { Vhi, Vlo, Wahi, Walo };
        ba.g[1][1] = { Uhi, Ulo, Wfhi, Wflo };                        ba.ng[1] = 2;
        ba.g[2][0] = { Vhi, Vlo, Wfhi, Wflo };                        ba.ng[2] = 1;
        ba.outC[0] = part;
        ba.outC[1] = part + (long)KS * PE_S;
        ba.outC[2] = part + (long)2 * KS * PE_S;
        mma_gemm64<64, 8, 512, 512, false, 2, KS, true, 2>
            <<<dim3(8, KS, 3), thr, 2 * STG_B(64)>>>(
            ba, PE_S, nullptr, nullptr, nullptr, nullptr, nullptr, nullptr, FAP);
    }

    // K4: reduce{U20..U22} + rankB
    k4_redu2_rankB<<<640, thr>>>(W_U1);

    // round 3 (split-K): {T0..T3} partials
    {
        BatchArgs ba{};
        ba.g[0][0] = { U20hi, U20lo, Wahi, Walo };                    ba.ng[0] = 1;
        ba.g[1][0] = { U21hi, U21lo, Wahi, Walo };
        ba.g[1][1] = { U20hi, U20lo, Wfhi, Wflo };                    ba.ng[1] = 2;
        ba.g[2][0] = { U22hi, U22lo, Wahi, Walo };
        ba.g[2][1] = { U21hi, U21lo, Wfhi, Wflo };                    ba.ng[2] = 2;
        ba.g[3][0] = { U22hi, U22lo, Wfhi, Wflo };                    ba.ng[3] = 1;
        ba.outC[0] = part;
        ba.outC[1] = part + (long)KS * PE_S;
        ba.outC[2] = part + (long)2 * KS * PE_S;
        ba.outC[3] = part + (long)3 * KS * PE_S;
        mma_gemm64<64, 8, 512, 512, false, 2, KS, true, 2>
            <<<dim3(8, KS, 4), thr, 2 * STG_B(64)>>>(
            ba, PE_S, nullptr, nullptr, nullptr, nullptr, nullptr, nullptr, FAP);
    }
    reduce_T_kernel<<<dim3(16, 4, 4), 256>>>();

    // mega GEMM: out = X@T0 + SX@T1 + SSX@T2 + S3X@T3 + rank24
    // KCH=32, single-acc, OCC=3 -> 444 concurrent slots, 2 waves.
    {
        BatchArgs ba{};
        ba.g[0][0] = { Xhi,   Xlo,   Tthi[0], Ttlo[0] };
        ba.g[0][1] = { SXhi,  SXlo,  Tthi[1], Ttlo[1] };
        ba.g[0][2] = { SSXhi, SSXlo, Tthi[2], Ttlo[2] };
        ba.g[0][3] = { S3Xhi, S3Xlo, Tthi[3], Ttlo[3] };
        ba.ng[0] = 4;
        ba.outC[0] = out;
        mma_gemm64<32, 4, 128, 512, true, 2, 1, false, 3>
            <<<dim3(8, 90, 1), thr, 2 * STG_B(32)>>>(
            ba, 0, sb, Ssb, SSsb, R0, R1, R2, MN);
    }
}

// round 17
// speedup vs baseline: 1.0473x; 1.0473x over previous
#include <cuda_runtime.h>
#include <cuda_bf16.h>
#include <cstdint>

// Problem constants (fixed by the dataset)
#define BDIM 76
#define NDIM 151
#define KNEI 10
#define HDIM 512
#define FB 5
#define FA 89
#define FAP 128                   // padded raw-input K
#define MN (BDIM * NDIM)          // 11476 nodes
#define MN2 (MN / 2)              // 5738 (two nodes per 256-thr block)
#define LDU2 (HDIM + FB)          // 517
#define LDU1 (2 * HDIM)           // 1024
#define KS 8                      // chain split-K factor
#define PE_S (FAP * HDIM)         // 65536 chain partial elems
#define PE_W (HDIM * HDIM)        // 262144 Wf partial elems

// ---------------- static device scratch (no allocation allowed) -------------
__device__ __align__(128) float g_sb[MN * 8], g_Ssb[MN * 8], g_SSsb[MN * 8];
__device__ __align__(128) float g_wc8[HDIM * 8], g_P1[HDIM * 8], g_P2[HDIM * 8];
__device__ __align__(128) float g_R0[HDIM * 8], g_R1[HDIM * 8], g_R2[HDIM * 8];
__device__ __align__(128) float g_Wf[HDIM * HDIM];
__device__ __align__(128) float g_SX[MN * FAP], g_SSX[MN * FAP];
__device__ __align__(128) float g_part[6 * KS * PE_S];     // split-K partials

__device__ __align__(128) __nv_bfloat16 g_Xhi[MN * FAP],   g_Xlo[MN * FAP];
__device__ __align__(128) __nv_bfloat16 g_SXhi[MN * FAP],  g_SXlo[MN * FAP];
__device__ __align__(128) __nv_bfloat16 g_SSXhi[MN * FAP], g_SSXlo[MN * FAP];
__device__ __align__(128) __nv_bfloat16 g_S3Xhi[MN * FAP], g_S3Xlo[MN * FAP];
__device__ __align__(128) __nv_bfloat16 g_Wahi[HDIM * HDIM], g_Walo[HDIM * HDIM];
__device__ __align__(128) __nv_bfloat16 g_Wbhi[HDIM * HDIM], g_Wblo[HDIM * HDIM];
__device__ __align__(128) __nv_bfloat16 g_Wthi[HDIM * HDIM], g_Wtlo[HDIM * HDIM];
__device__ __align__(128) __nv_bfloat16 g_Wfhi[HDIM * HDIM], g_Wflo[HDIM * HDIM];
__device__ __align__(128) __nv_bfloat16 g_Wethi[FAP * HDIM], g_Wetlo[FAP * HDIM];
// chain intermediates, in-major [128,512]
__device__ __align__(128) __nv_bfloat16 g_Uhi[FAP * HDIM],   g_Ulo[FAP * HDIM];
__device__ __align__(128) __nv_bfloat16 g_Vhi[FAP * HDIM],   g_Vlo[FAP * HDIM];
__device__ __align__(128) __nv_bfloat16 g_U20hi[FAP * HDIM], g_U20lo[FAP * HDIM];
__device__ __align__(128) __nv_bfloat16 g_U21hi[FAP * HDIM], g_U21lo[FAP * HDIM];
__device__ __align__(128) __nv_bfloat16 g_U22hi[FAP * HDIM], g_U22lo[FAP * HDIM];
// transposed T weights, B-format [512,128]
__device__ __align__(128) __nv_bfloat16 g_Tthi[4][HDIM * FAP], g_Ttlo[4][HDIM * FAP];

// ======================= PTX helpers (sm_80-safe only) ======================
__device__ __forceinline__ uint32_t smem_u32(const void* p) {
    uint32_t a;
    asm("{ .reg .u64 t; cvta.to.shared.u64 t, %1; cvt.u32.u64 %0, t; }"
        : "=r"(a) : "l"(p));
    return a;
}
__device__ __forceinline__ void cp_async16(uint32_t dst, const void* src, int sz) {
    asm volatile("cp.async.cg.shared.global [%0], [%1], 16, %2;"
                 :: "r"(dst), "l"(src), "r"(sz) : "memory");
}
__device__ __forceinline__ void ldsm_x4(uint32_t addr, uint32_t* r) {
    asm volatile("ldmatrix.sync.aligned.m8n8.x4.shared.b16 {%0,%1,%2,%3}, [%4];"
                 : "=r"(r[0]), "=r"(r[1]), "=r"(r[2]), "=r"(r[3]) : "r"(addr));
}
__device__ __forceinline__ void mma_bf16(float* c, const uint32_t* a,
                                         uint32_t b0, uint32_t b1) {
    asm volatile(
        "mma.sync.aligned.m16n8k16.row.col.f32.bf16.bf16.f32 "
        "{%0,%1,%2,%3}, {%4,%5,%6,%7}, {%8,%9}, {%0,%1,%2,%3};"
        : "+f"(c[0]), "+f"(c[1]), "+f"(c[2]), "+f"(c[3])
        : "r"(a[0]), "r"(a[1]), "r"(a[2]), "r"(a[3]), "r"(b0), "r"(b1));
}
__device__ __forceinline__ __nv_bfloat162 split_hi2(float x, float y,
                                                    __nv_bfloat162& lo2) {
    const __nv_bfloat16 hx = __float2bfloat16_rn(x);
    const __nv_bfloat16 hy = __float2bfloat16_rn(y);
    lo2 = __nv_bfloat162(__float2bfloat16_rn(x - __bfloat162float(hx)),
                         __float2bfloat16_rn(y - __bfloat162float(hy)));
    return __nv_bfloat162(hx, hy);
}
__device__ __forceinline__ float dot8(const float* s, const float* w) {
    return s[0]*w[0] + s[1]*w[1] + s[2]*w[2] + s[3]*w[3]
         + s[4]*w[4] + s[5]*w[5] + s[6]*w[6] + s[7]*w[7];
}

// ============ fused bf16x3 mma GEMM, 128x64 tiles ===========================
// Per z and group g: C += Ahi@Bhi^T + Alo@Bhi^T + Ahi@Blo^T
// KCH=64 throughout (proven config). Stage = 384 rows x 128B = 48KB.
#define STG_BYTES 49152

struct Grp { const __nv_bfloat16 *ahi, *alo, *bhi, *blo; };
struct BatchArgs {
    Grp g[6][4];                       // [z][group]
    int ng[6];
    float* outC[6];
};

template <int KCPP, int LDA, int LDC, bool RANK24, int NSTAGE, int KSPLIT>
__global__ __launch_bounds__(256, 2)
void mma_gemm64(const BatchArgs ba, int partElems,
                const float* __restrict__ sb0, const float* __restrict__ sb1,
                const float* __restrict__ sb2,
                const float* __restrict__ R0, const float* __restrict__ R1,
                const float* __restrict__ R2, int M) {
    extern __shared__ __align__(128) char smem[];
    const uint32_t sbase = smem_u32(smem);
    const int z = blockIdx.z;
    const Grp* G = ba.g[z];
    const int tid = threadIdx.x, wid = tid >> 5, lane = tid & 31;
    const int kslice = (KSPLIT > 1) ? ((int)blockIdx.y % KSPLIT) : 0;
    const int bm = ((KSPLIT > 1) ? ((int)blockIdx.y / KSPLIT) : blockIdx.y) * 128;
    const int bn = blockIdx.x * 64;
    const int wm = (wid & 3) * 32;
    const int wn = (wid >> 2) * 32;

    float accA[2][4][4] = {};
    float accB[2][4][4] = {};

    const int lrow0 = tid >> 3;
    const int lch = tid & 7;
    auto load_stage = [&](int g, int s) {
        const int grp = g / KCPP, kc = g % KCPP;
        const uint32_t sbs = sbase + s * STG_BYTES;
        const __nv_bfloat16* TA[2] = { G[grp].ahi, G[grp].alo };
        #pragma unroll
        for (int t = 0; t < 2; ++t) {
            const uint32_t tb = sbs + t * 16384;
            #pragma unroll
            for (int it = 0; it < 4; ++it) {
                const int row = lrow0 + it * 32;
                const uint32_t soff = row * 128 + ((lch ^ (row & 7)) << 4);
                const long gr = bm + row;
                cp_async16(tb + soff, TA[t] + gr * LDA + kc * 64 + lch * 8,
                           (gr < M) ? 16 : 0);
            }
        }
        const __nv_bfloat16* TB[2] = { G[grp].bhi, G[grp].blo };
        #pragma unroll
        for (int t = 0; t < 2; ++t) {
            const uint32_t tb = sbs + 32768 + t * 8192;
            #pragma unroll
            for (int it = 0; it < 2; ++it) {
                const int row = lrow0 + it * 32;
                const uint32_t soff = row * 128 + ((lch ^ (row & 7)) << 4);
                const long gr = bn + row;
                cp_async16(tb + soff, TB[t] + gr * LDA + kc * 64 + lch * 8, 16);
            }
        }
        asm volatile("cp.async.commit_group;" ::: "memory");
    };

    auto compute_stage = [&](int s) {
        const uint32_t sah = sbase + s * STG_BYTES;
        const uint32_t sal = sah + 16384;
        const uint32_t sbh = sah + 32768;
        const uint32_t sbl = sah + 40960;
        #pragma unroll
        for (int ks = 0; ks < 4; ++ks) {
            const int ach = ks * 2 + (lane >> 4);
            uint32_t rah[2][4], ral[2][4];
            #pragma unroll
            for (int mb = 0; mb < 2; ++mb) {
                const int row = wm + mb * 16 + (lane & 15);
                const uint32_t off = row * 128 + ((ach ^ (row & 7)) << 4);
                ldsm_x4(sah + off, rah[mb]);
                ldsm_x4(sal + off, ral[mb]);
            }
            uint32_t rbh[2][4], rbl[2][4];
            #pragma unroll
            for (int nb = 0; nb < 2; ++nb) {
                const int row = wn + nb * 16 + (lane & 15);
                const uint32_t off = row * 128 + ((ach ^ (row & 7)) << 4);
                ldsm_x4(sbh + off, rbh[nb]);
                ldsm_x4(sbl + off, rbl[nb]);
            }
            #pragma unroll
            for (int mb = 0; mb < 2; ++mb)
                #pragma unroll
                for (int nb = 0; nb < 2; ++nb) {
                    mma_bf16(accA[mb][nb * 2],     rah[mb], rbh[nb][0], rbh[nb][2]);
                    mma_bf16(accA[mb][nb * 2 + 1], rah[mb], rbh[nb][1], rbh[nb][3]);
                }
            #pragma unroll
            for (int mb = 0; mb < 2; ++mb)
                #pragma unroll
                for (int nb = 0; nb < 2; ++nb) {
                    mma_bf16(accB[mb][nb * 2],     ral[mb], rbh[nb][0], rbh[nb][2]);
                    mma_bf16(accB[mb][nb * 2 + 1], ral[mb], rbh[nb][1], rbh[nb][3]);
                }
            #pragma unroll
            for (int mb = 0; mb < 2; ++mb)
                #pragma unroll
                for (int nb = 0; nb < 2; ++nb) {
                    mma_bf16(accB[mb][nb * 2],     rah[mb], rbl[nb][0], rbl[nb][2]);
                    mma_bf16(accB[mb][nb * 2 + 1], rah[mb], rbl[nb][1], rbl[nb][3]);
                }
        }
    };

    const int NGt = ba.ng[z] * KCPP;
    const int per = (KSPLIT > 1) ? NGt / KSPLIT : NGt;
    const int g0 = kslice * per;
    load_stage(g0, g0 % NSTAGE);
    if (NSTAGE >= 3 && per > 1) load_stage(g0 + 1, (g0 + 1) % NSTAGE);
    for (int gi = 0; gi < per; ++gi) {
        const int g = g0 + gi;
        if (NSTAGE == 2) {
            if (gi + 1 < per) {
                load_stage(g + 1, (g + 1) % NSTAGE);
                asm volatile("cp.async.wait_group 1;" ::: "memory");
            } else {
                asm volatile("cp.async.wait_group 0;" ::: "memory");
            }
        } else {
            if (gi + 2 < per) {
                load_stage(g + 2, (g + 2) % NSTAGE);
                asm volatile("cp.async.wait_group 2;" ::: "memory");
            } else if (gi + 1 < per) {
                asm volatile("cp.async.wait_group 1;" ::: "memory");
            } else {
                asm volatile("cp.async.wait_group 0;" ::: "memory");
            }
        }
        __syncthreads();
        compute_stage(g % NSTAGE);
        __syncthreads();
    }

    if (RANK24) {
        #pragma unroll
        for (int t = 0; t < 3; ++t) {
            const float* sbp = (t == 0) ? sb0 : (t == 1) ? sb1 : sb2;
            const float* Rp  = (t == 0) ? R0  : (t == 1) ? R1  : R2;
            float sv[4][8];
            #pragma unroll
            for (int r = 0; r < 4; ++r) {
                const int gm = bm + wm + (r >> 1) * 16 + (lane >> 2) + (r & 1) * 8;
                if (gm < M) {
                    *(float4*)&sv[r][0] = *(const float4*)&sbp[gm * 8];
                    *(float4*)&sv[r][4] = *(const float4*)&sbp[gm * 8 + 4];
                } else {
                    #pragma unroll
                    for (int j = 0; j < 8; ++j) sv[r][j] = 0.f;
                }
            }
            #pragma unroll
            for (int nb = 0; nb < 4; ++nb) {
                const int gn = bn + wn + nb * 8 + (lane & 3) * 2;
                float w0[8], w1[8];
                *(float4*)&w0[0] = *(const float4*)&Rp[gn * 8];
                *(float4*)&w0[4] = *(const float4*)&Rp[gn * 8 + 4];
                *(float4*)&w1[0] = *(const float4*)&Rp[(gn + 1) * 8];
                *(float4*)&w1[4] = *(const float4*)&Rp[(gn + 1) * 8 + 4];
                #pragma unroll
                for (int mb = 0; mb < 2; ++mb)
                    #pragma unroll
                    for (int h = 0; h < 2; ++h) {
                        const int r = mb * 2 + h;
                        accA[mb][nb][h * 2]     += dot8(sv[r], w0);
                        accA[mb][nb][h * 2 + 1] += dot8(sv[r], w1);
                    }
            }
        }
    }

    float* C = ba.outC[z] + ((KSPLIT > 1) ? (long)kslice * partElems : 0);
    #pragma unroll
    for (int nb = 0; nb < 4; ++nb) {
        const int gn = bn + wn + nb * 8 + (lane & 3) * 2;
        #pragma unroll
        for (int mb = 0; mb < 2; ++mb)
            #pragma unroll
            for (int h = 0; h < 2; ++h) {
                const int gm = bm + wm + mb * 16 + (lane >> 2) + h * 8;
                if (gm < M) {
                    const float vx = accA[mb][nb][h * 2] + accB[mb][nb][h * 2];
                    const float vy = accA[mb][nb][h * 2 + 1] + accB[mb][nb][h * 2 + 1];
                    *(float2*)&C[(long)gm * LDC + gn] = make_float2(vx, vy);
                }
            }
    }
}

// ================= device sub-kernels (merged-launch parts) =================
__device__ void do_prep0(int b, int tid,
                         const float* __restrict__ W_U1,
                         const float* __restrict__ W_U2,
                         const float* __restrict__ W_atom,
                         const float* __restrict__ b_U2,
                         const float* __restrict__ b_U1, float* sh) {
    if (b < 2048) {
        const int koff = (b < 1024) ? 0 : HDIM;
        __nv_bfloat16* hi = (b < 1024) ? g_Wahi : g_Wbhi;
        __nv_bfloat16* lo = (b < 1024) ? g_Walo : g_Wblo;
        const int idx = (b & 1023) * 256 + tid;
        const int n = idx >> 9, k = idx & 511;
        const float v = __ldg(&W_U1[(long)n * LDU1 + koff + k]);
        const __nv_bfloat16 h = __float2bfloat16_rn(v);
        hi[idx] = h;
        lo[idx] = __float2bfloat16_rn(v - __bfloat162float(h));
    } else if (b < 2304) {
        const int bb = b - 2048;
        const int bx = (bb & 15) * 32, by = (bb >> 4) * 32;
        const int x = tid & 31, y = tid >> 5;
        #pragma unroll
        for (int i = 0; i < 32; i += 8)
            sh[(y + i) * 33 + x] = __ldg(&W_U2[(long)(by + y + i) * LDU2 + bx + x]);
        __syncthreads();
        #pragma unroll
        for (int i = 0; i < 32; i += 8) {
            const float v = sh[x * 33 + y + i];
            const __nv_bfloat16 h = __float2bfloat16_rn(v);
            const long o = (long)(bx + y + i) * HDIM + by + x;
            g_Wthi[o] = h;
            g_Wtlo[o] = __float2bfloat16_rn(v - __bfloat162float(h));
        }
    } else if (b < 2352) {
        const int bb = b - 2304;
        const int bm = (bb % 16) * 32, bf = (bb / 16) * 32;
        const int x = tid & 31, y = tid >> 5;
        #pragma unroll
        for (int i = 0; i < 32; i += 8) {
            const int m = bm + y + i, f = bf + x;
            sh[(y + i) * 33 + x] = (f < FA) ? __ldg(&W_atom[(long)m * FA + f]) : 0.f;
        }
        __syncthreads();
        #pragma unroll
        for (int i = 0; i < 32; i += 8) {
            const int f = bf + y + i, m = bm + x;
            if (f < FA) {
                const float v = sh[x * 33 + y + i];
                const __nv_bfloat16 h = __float2bfloat16_rn(v);
                const long o = (long)f * HDIM + m;
                g_Wethi[o] = h;
                g_Wetlo[o] = __float2bfloat16_rn(v - __bfloat162float(h));
            }
        }
    } else {
        const int h = b - 2352;
        const int w = tid >> 5, lane = tid & 31;
        float acc[6] = {};
        #pragma unroll
        for (int j = 0; j < 2; ++j) {
            const int m = tid + 256 * j;
            const float u = __ldg(&W_U1[(long)h * LDU1 + HDIM + m]);
            #pragma unroll
            for (int f = 0; f < FB; ++f)
                acc[f] += u * __ldg(&W_U2[(long)m * LDU2 + HDIM + f]);
            acc[5] += u * __ldg(&b_U2[m]);
        }
        #pragma unroll
        for (int f = 0; f < 6; ++f)
            #pragma unroll
            for (int o = 16; o; o >>= 1)
                acc[f] += __shfl_xor_sync(0xFFFFFFFF, acc[f], o);
        if (lane == 0)
            #pragma unroll
            for (int f = 0; f < 6; ++f) sh[w * 8 + f] = acc[f];
        __syncthreads();
        if (tid == 0) {
            float r[6];
            #pragma unroll
            for (int f = 0; f < 6; ++f) {
                r[f] = 0.f;
                #pragma unroll
                for (int ww = 0; ww < 8; ++ww) r[f] += sh[ww * 8 + f];
            }
            *(float4*)&g_wc8[h * 8] = make_float4(r[0], r[1], r[2], r[3]);
            *(float4*)&g_wc8[h * 8 + 4] = make_float4(r[4], r[5],
                                                      __ldg(&b_U1[h]), 0.f);
        }
    }
}

__device__ void do_pgather(int node, int c,
                           const float* __restrict__ P,
                           const float* __restrict__ input_bond,
                           const int* __restrict__ aidx,
                           const int* __restrict__ bidx,
                           const int* __restrict__ num_nbs) {
    const int base = (node / NDIM) * NDIM;
    const int nn = num_nbs[node];
    const float v = (c < FA) ? __ldg(&P[(long)node * FA + c]) : 0.f;
    const __nv_bfloat16 vh = __float2bfloat16_rn(v);
    g_Xhi[(long)node * FAP + c] = vh;
    g_Xlo[(long)node * FAP + c] = __float2bfloat16_rn(v - __bfloat162float(vh));

    float s = 0.f;
    if (c < FA) {
        #pragma unroll
        for (int k = 0; k < KNEI; ++k) {
            if (k >= nn) break;
            const int idx = __ldg(&aidx[((long)node * KNEI + k) * 2]);
            s += __ldg(&P[(long)(base + idx) * FA + c]);
        }
    }
    g_SX[(long)node * FAP + c] = s;
    const __nv_bfloat16 sh = __float2bfloat16_rn(s);
    g_SXhi[(long)node * FAP + c] = sh;
    g_SXlo[(long)node * FAP + c] = __float2bfloat16_rn(s - __bfloat162float(sh));

    if (c < 8) {
        float sv;
        if (c < FB) {
            sv = 0.f;
            for (int k = 0; k < nn; ++k) {
                const int idx = __ldg(&bidx[((long)node * KNEI + k) * 2]);
                sv += __ldg(&input_bond[(long)(base + idx) * FB + c]);
            }
        } else sv = (c == 5) ? (float)nn : (c == 6) ? 1.f : 0.f;
        g_sb[node * 8 + c] = sv;
    }
}

__device__ void do_gatherK(int node, int c, bool wf32,
                           const float* __restrict__ in, float* __restrict__ outf,
                           __nv_bfloat16* __restrict__ ohi,
                           __nv_bfloat16* __restrict__ olo,
                           const float* __restrict__ sbin, float* __restrict__ sbout,
                           const int* __restrict__ aidx,
                           const int* __restrict__ num_nbs) {
    const int base = (node / NDIM) * NDIM;
    const int nn = num_nbs[node];
    float s = 0.f;
    float sb = 0.f;
    #pragma unroll
    for (int k = 0; k < KNEI; ++k) {
        if (k >= nn) break;
        const int idx = __ldg(&aidx[((long)node * KNEI + k) * 2]);
        s += __ldg(&in[(long)(base + idx) * FAP + c]);
        if (c < 8) sb += __ldg(&sbin[(base + idx) * 8 + c]);
    }
    if (wf32) outf[(long)node * FAP + c] = s;
    const __nv_bfloat16 sh = __float2bfloat16_rn(s);
    ohi[(long)node * FAP + c] = sh;
    olo[(long)node * FAP + c] = __float2bfloat16_rn(s - __bfloat162float(sh));
    if (c < 8) sbout[node * 8 + c] = sb;
}

__device__ void do_reduce_wf(int b, int tid) {
    const int i = (b * 256 + tid) * 2;
    float2 s = make_float2(0.f, 0.f);
    #pragma unroll
    for (int sl = 0; sl < KS; ++sl) {
        const float2 v = *(const float2*)&g_part[sl * PE_W + i];
        s.x += v.x; s.y += v.y;
    }
    *(float2*)&g_Wf[i] = s;
    __nv_bfloat162 lo2;
    const __nv_bfloat162 hi2 = split_hi2(s.x, s.y, lo2);
    *(__nv_bfloat162*)&g_Wfhi[i] = hi2;
    *(__nv_bfloat162*)&g_Wflo[i] = lo2;
}

// sum nsl contiguous slices starting at base -> bf16 hi/lo
__device__ void do_reduce_split(const float* base, int nsl, int bi, int tid,
                                __nv_bfloat16* hi, __nv_bfloat16* lo) {
    const int i = (bi * 256 + tid) * 2;
    float2 s = make_float2(0.f, 0.f);
    for (int sl = 0; sl < nsl; ++sl) {
        const float2 v = *(const float2*)&base[(long)sl * PE_S + i];
        s.x += v.x; s.y += v.y;
    }
    __nv_bfloat162 lo2;
    const __nv_bfloat162 hi2 = split_hi2(s.x, s.y, lo2);
    *(__nv_bfloat162*)&hi[i] = hi2;
    *(__nv_bfloat162*)&lo[i] = lo2;
}

__device__ void do_rankA(int blk, int tid, const float* __restrict__ W_U1) {
    const int w = tid >> 5, lane = tid & 31;
    const int n = blk * 4 + (w & 3);
    const bool useWf = (w >> 2) != 0;
    float acc[8] = {};
    for (int m = lane; m < HDIM; m += 32) {
        const float u = useWf ? g_Wf[(long)n * HDIM + m]
                              : __ldg(&W_U1[(long)n * LDU1 + m]);
        #pragma unroll
        for (int j = 0; j < 8; ++j) acc[j] += u * g_wc8[m * 8 + j];
    }
    #pragma unroll
    for (int j = 0; j < 8; ++j)
        #pragma unroll
        for (int o = 16; o; o >>= 1)
            acc[j] += __shfl_xor_sync(0xFFFFFFFF, acc[j], o);
    if (lane == 0) {
        float* dst = useWf ? g_P2 : g_P1;
        #pragma unroll
        for (int j = 0; j < 8; ++j) dst[n * 8 + j] = acc[j];
    }
}

__device__ void do_rankB(int blk, int tid, const float* __restrict__ W_U1,
                         float* sh) {
    const int w = tid >> 5, lane = tid & 31;
    const int half = w >> 2;
    const int role = w & 3;
    const int n = blk * 2 + half;
    const bool useWa = (role == 0 || role == 2);
    const bool usePw = (role < 2);
    float acc[8] = {};
    for (int m = lane; m < HDIM; m += 32) {
        const float u = useWa ? __ldg(&W_U1[(long)n * LDU1 + m])
                              : g_Wf[(long)n * HDIM + m];
        #pragma unroll
        for (int j = 0; j < 8; ++j) {
            const float rv = usePw ? (g_P1[m * 8 + j] + g_wc8[m * 8 + j])
                                   : g_P2[m * 8 + j];
            acc[j] += u * rv;
        }
    }
    #pragma unroll
    for (int j = 0; j < 8; ++j)
        #pragma unroll
        for (int o = 16; o; o >>= 1)
            acc[j] += __shfl_xor_sync(0xFFFFFFFF, acc[j], o);
    if (lane == 0)
        #pragma unroll
        for (int j = 0; j < 8; ++j) sh[(half * 4 + role) * 8 + j] = acc[j];
    __syncthreads();
    if (lane == 0 && role == 0) {
        const float* bsh = &sh[half * 4 * 8];
        #pragma unroll
        for (int j = 0; j < 8; ++j) {
            g_R0[n * 8 + j] = bsh[0 * 8 + j] + g_wc8[n * 8 + j];
            g_R1[n * 8 + j] = bsh[2 * 8 + j] + bsh[1 * 8 + j];
            g_R2[n * 8 + j] = bsh[3 * 8 + j];
        }
    }
}

// ================= merged launch kernels ====================================
__global__ __launch_bounds__(256)
void k1_prep_pgather(const float* __restrict__ W_U1,
                     const float* __restrict__ W_U2,
                     const float* __restrict__ W_atom,
                     const float* __restrict__ b_U2,
                     const float* __restrict__ b_U1,
                     const float* __restrict__ input_atom,
                     const float* __restrict__ input_bond,
                     const int* __restrict__ aidx,
                     const int* __restrict__ bidx,
                     const int* __restrict__ num_nbs) {
    __shared__ float sh[32 * 33];
    const int b = blockIdx.x, tid = threadIdx.x;
    if (b < 2864) {
        do_prep0(b, tid, W_U1, W_U2, W_atom, b_U2, b_U1, sh);
    } else {
        const int node = (b - 2864) * 2 + (tid >> 7);
        do_pgather(node, tid & 127, input_atom, input_bond, aidx, bidx, num_nbs);
    }
}

__global__ __launch_bounds__(256)
void k2_redwf_gather1(const int* __restrict__ aidx,
                      const int* __restrict__ num_nbs) {
    const int b = blockIdx.x, tid = threadIdx.x;
    if (b < 512) {
        do_reduce_wf(b, tid);
    } else {
        const int node = (b - 512) * 2 + (tid >> 7);
        do_gatherK(node, tid & 127, true, g_SX, g_SSX, g_SSXhi, g_SSXlo,
                   g_sb, g_Ssb, aidx, num_nbs);
    }
}

__global__ __launch_bounds__(256)
void k3_reduv_rankA_gather2(const float* __restrict__ W_U1,
                            const int* __restrict__ aidx,
                            const int* __restrict__ num_nbs) {
    const int b = blockIdx.x, tid = threadIdx.x;
    if (b < 256) {
        const int z = b >> 7, bi = b & 127;
        do_reduce_split(g_part + (long)z * KS * PE_S, KS, bi, tid,
                        z ? g_Vhi : g_Uhi, z ? g_Vlo : g_Ulo);
    } else if (b < 384) {
        do_rankA(b - 256, tid, W_U1);
    } else {
        const int node = (b - 384) * 2 + (tid >> 7);
        do_gatherK(node, tid & 127, false, g_SSX, nullptr, g_S3Xhi, g_S3Xlo,
                   g_Ssb, g_SSsb, aidx, num_nbs);
    }
}

// K4: reduce U20=set0(8), U21=sets1+2(16), U22=set3(8); rankB
__global__ __launch_bounds__(256)
void k4_redu2_rankB(const float* __restrict__ W_U1) {
    __shared__ float sh[64];
    const int b = blockIdx.x, tid = threadIdx.x;
    if (b < 384) {
        const int z = b >> 7, bi = b & 127;
        const int set0 = (z == 0) ? 0 : (z == 1) ? 1 : 3;
        const int nsl = (z == 1) ? 2 * KS : KS;
        __nv_bfloat16* hi = (z == 0) ? g_U20hi : (z == 1) ? g_U21hi : g_U22hi;
        __nv_bfloat16* lo = (z == 0) ? g_U20lo : (z == 1) ? g_U21lo : g_U22lo;
        do_reduce_split(g_part + (long)set0 * KS * PE_S, nsl, bi, tid, hi, lo);
    } else {
        do_rankB(b - 384, tid, W_U1, sh);
    }
}

// reduce_T: T0=set0(8), T1=sets1+2(16), T2=sets3+4(16), T3=set5(8); transpose
__global__ __launch_bounds__(256)
void reduce_T_kernel() {
    __shared__ float sh[32 * 33];
    const int z = blockIdx.z;
    const int set0 = (z == 0) ? 0 : (z == 1) ? 1 : (z == 2) ? 3 : 5;
    const int nsl = (z == 1 || z == 2) ? 2 * KS : KS;
    const float* base = g_part + (long)set0 * KS * PE_S;
    __nv_bfloat16* ohi = g_Tthi[z];
    __nv_bfloat16* olo = g_Ttlo[z];
    const int bn = blockIdx.x * 32, bk = blockIdx.y * 32;
    const int x = threadIdx.x & 31, y = threadIdx.x >> 5;
    #pragma unroll
    for (int i = 0; i < 32; i += 8) {
        float s = 0.f;
        for (int sl = 0; sl < nsl; ++sl)
            s += __ldg(&base[(long)sl * PE_S + (bk + y + i) * HDIM + bn + x]);
        sh[(y + i) * 33 + x] = s;
    }
    __syncthreads();
    #pragma unroll
    for (int i = 0; i < 32; i += 8) {
        const float v = sh[x * 33 + y + i];
        const __nv_bfloat16 h = __float2bfloat16_rn(v);
        const long o = (long)(bn + y + i) * FAP + bk + x;
        ohi[o] = h;
        olo[o] = __float2bfloat16_rn(v - __bfloat162float(h));
    }
}

// ======================= host ===============================================
extern "C" void kernel_launch(void* const* d_in, const int* in_sizes, int n_in,
                              void* d_out, int out_size) {
    const float* input_atom = (const float*)d_in[0];
    const float* input_bond = (const float*)d_in[1];
    const int*   atom_nei   = (const int*)d_in[2];
    const int*   bond_nei   = (const int*)d_in[3];
    const int*   num_nbs    = (const int*)d_in[4];
    const float* W_atom     = (const float*)d_in[5];
    const float* W_U2       = (const float*)d_in[6];
    const float* b_U2       = (const float*)d_in[7];
    const float* W_U1       = (const float*)d_in[8];
    const float* b_U1       = (const float*)d_in[9];
    float* out = (float*)d_out;

    #define GA(p, s) cudaGetSymbolAddress((void**)&p, s)
    float *sb, *Ssb, *SSsb, *R0, *R1, *R2, *part;
    GA(sb, g_sb); GA(Ssb, g_Ssb); GA(SSsb, g_SSsb);
    GA(R0, g_R0); GA(R1, g_R1); GA(R2, g_R2); GA(part, g_part);
    __nv_bfloat16 *Xhi, *Xlo, *SXhi, *SXlo, *SSXhi, *SSXlo, *S3Xhi, *S3Xlo;
    GA(Xhi, g_Xhi); GA(Xlo, g_Xlo); GA(SXhi, g_SXhi); GA(SXlo, g_SXlo);
    GA(SSXhi, g_SSXhi); GA(SSXlo, g_SSXlo); GA(S3Xhi, g_S3Xhi); GA(S3Xlo, g_S3Xlo);
    __nv_bfloat16 *Wahi, *Walo, *Wbhi, *Wblo, *Wthi, *Wtlo, *Wfhi, *Wflo;
    __nv_bfloat16 *Wethi, *Wetlo;
    GA(Wahi, g_Wahi); GA(Walo, g_Walo); GA(Wbhi, g_Wbhi); GA(Wblo, g_Wblo);
    GA(Wthi, g_Wthi); GA(Wtlo, g_Wtlo); GA(Wfhi, g_Wfhi); GA(Wflo, g_Wflo);
    GA(Wethi, g_Wethi); GA(Wetlo, g_Wetlo);
    __nv_bfloat16 *Uhi, *Ulo, *Vhi, *Vlo;
    __nv_bfloat16 *U20hi, *U20lo, *U21hi, *U21lo, *U22hi, *U22lo;
    GA(Uhi, g_Uhi); GA(Ulo, g_Ulo); GA(Vhi, g_Vhi); GA(Vlo, g_Vlo);
    GA(U20hi, g_U20hi); GA(U20lo, g_U20lo); GA(U21hi, g_U21hi);
    GA(U21lo, g_U21lo); GA(U22hi, g_U22hi); GA(U22lo, g_U22lo);
    __nv_bfloat16 (*Tthi)[HDIM * FAP], (*Ttlo)[HDIM * FAP];
    GA(Tthi, g_Tthi); GA(Ttlo, g_Ttlo);
    #undef GA

    cudaFuncSetAttribute((const void*)mma_gemm64<8, 512, 512, false, 2, KS>,
                         cudaFuncAttributeMaxDynamicSharedMemorySize, 2 * STG_BYTES);
    cudaFuncSetAttribute((const void*)mma_gemm64<2, 128, 512, true, 2, 1>,
                         cudaFuncAttributeMaxDynamicSharedMemorySize, 2 * STG_BYTES);

    const dim3 thr(256);

    // K1: fused prep + pgather
    k1_prep_pgather<<<2864 + MN2, thr>>>(W_U1, W_U2, W_atom, b_U2, b_U1,
                                         input_atom, input_bond,
                                         atom_nei, bond_nei, num_nbs);

    // round 0 (split-K): Wf partials = W_U1b @ W_U2a
    {
        BatchArgs ba{};
        ba.g[0][0] = { Wbhi, Wblo, Wthi, Wtlo };
        ba.ng[0] = 1; ba.outC[0] = part;
        mma_gemm64<8, 512, 512, false, 2, KS>
            <<<dim3(8, 4 * KS, 1), thr, 2 * STG_BYTES>>>(
            ba, PE_W, nullptr, nullptr, nullptr, nullptr, nullptr, nullptr, HDIM);
    }

    // K2: reduce_wf + gatherK1 (SSX)
    k2_redwf_gather1<<<512 + MN2, thr>>>(atom_nei, num_nbs);

    // round 1 (split-K): {U, V} = Wet o {Wa, Wf}
    {
        BatchArgs ba{};
        ba.g[0][0] = { Wethi, Wetlo, Wahi, Walo };
        ba.g[1][0] = { Wethi, Wetlo, Wfhi, Wflo };
        ba.ng[0] = ba.ng[1] = 1;
        ba.outC[0] = part;
        ba.outC[1] = part + (long)KS * PE_S;
        mma_gemm64<8, 512, 512, false, 2, KS>
            <<<dim3(8, KS, 2), thr, 2 * STG_BYTES>>>(
            ba, PE_S, nullptr, nullptr, nullptr, nullptr, nullptr, nullptr, FAP);
    }

    // K3: reduce{U,V} + rankA + gatherK2 (S3X)
    k3_reduv_rankA_gather2<<<384 + MN2, thr>>>(W_U1, atom_nei, num_nbs);

    // round 2 (flat split-K): sets {UWa, VWa, UWf, VWf}; ng=1 each
    {
        BatchArgs ba{};
        ba.g[0][0] = { Uhi, Ulo, Wahi, Walo };
        ba.g[1][0] = { Vhi, Vlo, Wahi, Walo };
        ba.g[2][0] = { Uhi, Ulo, Wfhi, Wflo };
        ba.g[3][0] = { Vhi, Vlo, Wfhi, Wflo };
        ba.ng[0] = ba.ng[1] = ba.ng[2] = ba.ng[3] = 1;
        for (int s = 0; s < 4; ++s) ba.outC[s] = part + (long)s * KS * PE_S;
        mma_gemm64<8, 512, 512, false, 2, KS>
            <<<dim3(8, KS, 4), thr, 2 * STG_BYTES>>>(
            ba, PE_S, nullptr, nullptr, nullptr, nullptr, nullptr, nullptr, FAP);
    }

    // K4: reduce{U20=s0, U21=s1+s2, U22=s3} + rankB
    k4_redu2_rankB<<<640, thr>>>(W_U1);

    // round 3 (flat split-K): sets {U20Wa, U21Wa, U20Wf, U22Wa, U21Wf, U22Wf}
    {
        BatchArgs ba{};
        ba.g[0][0] = { U20hi, U20lo, Wahi, Walo };
        ba.g[1][0] = { U21hi, U21lo, Wahi, Walo };
        ba.g[2][0] = { U20hi, U20lo, Wfhi, Wflo };
        ba.g[3][0] = { U22hi, U22lo, Wahi, Walo };
        ba.g[4][0] = { U21hi, U21lo, Wfhi, Wflo };
        ba.g[5][0] = { U22hi, U22lo, Wfhi, Wflo };
        for (int s = 0; s < 6; ++s) {
            ba.ng[s] = 1;
            ba.outC[s] = part + (long)s * KS * PE_S;
        }
        mma_gemm64<8, 512, 512, false, 2, KS>
            <<<dim3(8, KS, 6), thr, 2 * STG_BYTES>>>(
            ba, PE_S, nullptr, nullptr, nullptr, nullptr, nullptr, nullptr, FAP);
    }
    // reduce_T: T0=s0, T1=s1+s2, T2=s3+s4, T3=s5 (transposed hi/lo)
    reduce_T_kernel<<<dim3(16, 4, 4), 256>>>();

    // mega GEMM (R15-proven config): out = X@T0 + SX@T1 + SSX@T2 + S3X@T3 + rank24
    {
        BatchArgs ba{};
        ba.g[0][0] = { Xhi,   Xlo,   Tthi[0], Ttlo[0] };
        ba.g[0][1] = { SXhi,  SXlo,  Tthi[1], Ttlo[1] };
        ba.g[0][2] = { SSXhi, SSXlo, Tthi[2], Ttlo[2] };
        ba.g[0][3] = { S3Xhi, S3Xlo, Tthi[3], Ttlo[3] };
        ba.ng[0] = 4;
        ba.outC[0] = out;
        mma_gemm64<2, 128, 512, true, 2, 1>
            <<<dim3(8, 90, 1), thr, 2 * STG_BYTES>>>(
            ba, 0, sb, Ssb, SSsb, R0, R1, R2, MN);
    }
}